// round 17
// baseline (speedup 1.0000x reference)
#include <cuda_runtime.h>
#include <cuda_bf16.h>
#include <cstdint>

// Problem constants (fixed shapes from reference)
constexpr int B = 256;
constexpr int P = 1024;
constexpr int G = 128;
constexpr float DIST_T2 = 500.0f * 500.0f;   // compare squared distance
constexpr float BBOX_THRESH = 0.1f;
constexpr float SENTINEL = 1.0e15f;          // d2 ~ 3e30: finite, never ties/beats real

constexpr int THREADS = 128;
constexpr int IPROP   = 2;                     // proposals per thread
constexpr int PROPS_PER_CTA = THREADS * IPROP; // 256
constexpr int CHUNKS_PB = P / PROPS_PER_CTA;   // 4

__device__ __forceinline__ uint64_t pack2(float lo, float hi) {
    uint64_t r;
    asm("mov.b64 %0, {%1, %2};" : "=l"(r) : "f"(lo), "f"(hi));
    return r;
}

// d2 for a GT pair, entirely inside one asm block so the packed temporaries
// never leak into C++ register allocation. Inputs pre-negated: d = p + (-g).
// Deterministic: replaying with the same inputs gives bit-identical results.
__device__ __forceinline__ void d2pair(uint64_t X2, uint64_t Y2, uint64_t Z2,
                                       uint64_t gnx, uint64_t gny, uint64_t gnz,
                                       float& a, float& b) {
    asm("{\n\t"
        ".reg .b64 dx, dy, dz, acc;\n\t"
        "add.rn.f32x2 dx, %2, %4;\n\t"
        "add.rn.f32x2 dy, %3, %5;\n\t"
        "add.rn.f32x2 dz, %6, %7;\n\t"
        "mul.rn.f32x2 acc, dz, dz;\n\t"
        "fma.rn.f32x2 acc, dy, dy, acc;\n\t"
        "fma.rn.f32x2 acc, dx, dx, acc;\n\t"
        "mov.b64 {%0, %1}, acc;\n\t"
        "}"
        : "=f"(a), "=f"(b)
        : "l"(X2), "l"(Y2), "l"(gnx), "l"(gny), "l"(Z2), "l"(gnz));
}

__global__ __launch_bounds__(THREADS) void proposal_kernel(
    const float* __restrict__ topk_index,    // [B,P,3]
    const float* __restrict__ topk_confs,    // [B,P]
    const float* __restrict__ bbox_preds,    // [B,P,2]
    const float* __restrict__ gt_3d,         // [B,G,3]
    const float* __restrict__ gt_bbox,       // [B,G,2]
    const int*   __restrict__ num_person,    // [B]
    float*       __restrict__ out)           // [B,P,7]
{
    // Dense pair layout -> 3 x LDS.128 per 2 pairs (4 GT points), shared by
    // BOTH proposals of each thread:
    //   sxy[i] = ( (-gx_{2i},-gx_{2i+1}), (-gy_{2i},-gy_{2i+1}) )
    //   szz[k] = ( (-gz_{4k},-gz_{4k+1}), (-gz_{4k+2},-gz_{4k+3}) )
    __shared__ ulonglong2 sxy[G / 2];
    __shared__ ulonglong2 szz[G / 4];

    const int tid   = threadIdx.x;
    const int b     = blockIdx.x >> 2;        // 4 chunks per batch
    const int chunk = blockIdx.x & 3;
    const int n     = num_person[b];          // uniform per CTA

    // Stage GT negated (tid == g). Slots g >= n get the sentinel so the
    // padded, remainder-free loop is exact: real slots come first (n >= 1),
    // max real d2 ~ 1.92e8 << sentinel d2 ~ 3e30 (never ties, never wins).
    {
        float ngx = -SENTINEL, ngy = -SENTINEL, ngz = -SENTINEL;
        if (tid < n) {
            const float* g3 = gt_3d + ((size_t)b * G + tid) * 3;
            ngx = -g3[0]; ngy = -g3[1]; ngz = -g3[2];
        }
        float* fxy = reinterpret_cast<float*>(sxy);
        fxy[(tid >> 1) * 4 + (tid & 1)]     = ngx;   // x lane of pair tid>>1
        fxy[(tid >> 1) * 4 + 2 + (tid & 1)] = ngy;   // y lane
        reinterpret_cast<float*>(szz)[tid]  = ngz;   // z lanes, 4 per record
    }
    __syncthreads();

    // Two proposals per thread: p0 = base+tid, p1 = base+tid+128 (coalesced)
    const int    pbase = chunk * PROPS_PER_CTA + tid;
    const size_t bp0   = (size_t)b * P + pbase;
    const size_t bp1   = bp0 + THREADS;

    const float x0 = topk_index[bp0 * 3 + 0];
    const float y0 = topk_index[bp0 * 3 + 1];
    const float z0 = topk_index[bp0 * 3 + 2];
    const float x1 = topk_index[bp1 * 3 + 0];
    const float y1 = topk_index[bp1 * 3 + 1];
    const float z1 = topk_index[bp1 * 3 + 2];

    // Hoist per-proposal gmem loads so their latency overlaps the loop.
    const float q00 = bbox_preds[bp0 * 2 + 0];
    const float q01 = bbox_preds[bp0 * 2 + 1];
    const float q10 = bbox_preds[bp1 * 2 + 0];
    const float q11 = bbox_preds[bp1 * 2 + 1];
    const float c0  = topk_confs[bp0];
    const float c1  = topk_confs[bp1];

    const uint64_t X20 = pack2(x0, x0), Y20 = pack2(y0, y0), Z20 = pack2(z0, z0);
    const uint64_t X21 = pack2(x1, x1), Y21 = pack2(y1, y1), Z21 = pack2(z1, z1);

    // Min-tree per proposal: 4 distances/step -> one scalar min (3 FMNMX),
    // single (best, step) champion. Index recovered post-loop by replaying
    // the winning step (d2pair is bit-exact on replay).
    float best0 = 3.402823466e38f, best1 = 3.402823466e38f;
    int   kb0 = 0, kb1 = 0;

    const int nsteps = ((n + 7) & ~7) >> 2;   // 4 GT per step, no remainder
    #pragma unroll 2
    for (int k = 0; k < nsteps; ++k) {
        const ulonglong2 A0 = sxy[2 * k];      // pairs 2k   : LDS.128
        const ulonglong2 A1 = sxy[2 * k + 1];  // pairs 2k+1 : LDS.128
        const ulonglong2 Zk = szz[k];          // both z-pairs: LDS.128

        float a0, a1, a2, a3;                  // proposal 0
        d2pair(X20, Y20, Z20, A0.x, A0.y, Zk.x, a0, a1);
        d2pair(X20, Y20, Z20, A1.x, A1.y, Zk.y, a2, a3);
        float e0, e1, e2, e3;                  // proposal 1
        d2pair(X21, Y21, Z21, A0.x, A0.y, Zk.x, e0, e1);
        d2pair(X21, Y21, Z21, A1.x, A1.y, Zk.y, e2, e3);

        const float ma = fminf(fminf(a0, a1), fminf(a2, a3));
        const float me = fminf(fminf(e0, e1), fminf(e2, e3));

        const bool ca = ma < best0;            // strict < -> first step wins
        const bool ce = me < best1;
        best0 = fminf(best0, ma);  kb0 = ca ? k : kb0;
        best1 = fminf(best1, me);  kb1 = ce ? k : kb1;
    }

    // Replay the winning step per proposal; first lane equal to best is the
    // global first-index argmin (== JAX argmin; see R16 argument: strict <
    // made kb the FIRST step attaining the global min).
    int ga0, ga1;
    {
        const ulonglong2 A0 = sxy[2 * kb0];
        const ulonglong2 A1 = sxy[2 * kb0 + 1];
        const ulonglong2 Zk = szz[kb0];
        float a0, a1, a2, a3;
        d2pair(X20, Y20, Z20, A0.x, A0.y, Zk.x, a0, a1);
        d2pair(X20, Y20, Z20, A1.x, A1.y, Zk.y, a2, a3);
        int j = 3;
        if      (a0 == best0) j = 0;
        else if (a1 == best0) j = 1;
        else if (a2 == best0) j = 2;
        ga0 = 4 * kb0 + j;
    }
    {
        const ulonglong2 A0 = sxy[2 * kb1];
        const ulonglong2 A1 = sxy[2 * kb1 + 1];
        const ulonglong2 Zk = szz[kb1];
        float e0, e1, e2, e3;
        d2pair(X21, Y21, Z21, A0.x, A0.y, Zk.x, e0, e1);
        d2pair(X21, Y21, Z21, A1.x, A1.y, Zk.y, e2, e3);
        int j = 3;
        if      (e0 == best1) j = 0;
        else if (e1 == best1) j = 1;
        else if (e2 == best1) j = 2;
        ga1 = 4 * kb1 + j;
    }

    // dist > 500  <=>  d2 > 500^2 (sqrt monotone; compare-exact)
    const float p2g0 = (best0 > DIST_T2) ? -1.0f : (float)ga0;
    const float p2g1 = (best1 > DIST_T2) ? -1.0f : (float)ga1;

    // Matched GT bboxes: divergent LDG.64 (L2-hot), no smem staging.
    const float2 mb0 = reinterpret_cast<const float2*>(gt_bbox)[(size_t)b * G + ga0];
    const float2 mb1 = reinterpret_cast<const float2*>(gt_bbox)[(size_t)b * G + ga1];
    const bool cond0 = (p2g0 >= 0.0f) &&
                       ((q00 < mb0.x - BBOX_THRESH) || (q01 < mb0.y - BBOX_THRESH));
    const bool cond1 = (p2g1 >= 0.0f) &&
                       ((q10 < mb1.x - BBOX_THRESH) || (q11 < mb1.y - BBOX_THRESH));

    // Direct 7-float stores (contiguous 28B per proposal).
    {
        float* o = out + bp0 * 7;
        o[0] = x0;  o[1] = y0;  o[2] = z0;
        o[3] = p2g0; o[4] = c0;
        o[5] = cond0 ? mb0.x : q00;
        o[6] = cond0 ? mb0.y : q01;
    }
    {
        float* o = out + bp1 * 7;
        o[0] = x1;  o[1] = y1;  o[2] = z1;
        o[3] = p2g1; o[4] = c1;
        o[5] = cond1 ? mb1.x : q10;
        o[6] = cond1 ? mb1.y : q11;
    }
}

extern "C" void kernel_launch(void* const* d_in, const int* in_sizes, int n_in,
                              void* d_out, int out_size) {
    const float* topk_index  = (const float*)d_in[0];  // [B,P,3]
    const float* topk_confs  = (const float*)d_in[1];  // [B,P]
    const float* bbox_preds  = (const float*)d_in[2];  // [B,P,2]
    const float* gt_3d       = (const float*)d_in[3];  // [B,G,3]
    const float* gt_bbox     = (const float*)d_in[4];  // [B,G,2]
    const int*   num_person  = (const int*)  d_in[5];  // [B]
    float*       out         = (float*)d_out;          // [B,P,7]

    proposal_kernel<<<B * CHUNKS_PB, THREADS>>>(topk_index, topk_confs, bbox_preds,
                                                gt_3d, gt_bbox, num_person, out);
}